// round 1
// baseline (speedup 1.0000x reference)
#include <cuda_runtime.h>

// Problem constants (fixed by the dataset)
#define NN 100000   // nodes
#define EE 500000   // edges
#define ND 16       // node_dim
#define ED 8        // edge_dim
#define HD 16       // hidden_dim
#define NG 32       // graphs

// Scratch (no allocation allowed -> __device__ globals)
__device__ __align__(128) float g_v[(size_t)NN * HD * ED];   // 51.2 MB: v[n][o][d]
__device__ __align__(128) float g_bb[(size_t)NN * HD];       // bias-term per (node,o)
__device__ __align__(128) float g_agg1[(size_t)NN * HD];
__device__ __align__(128) float g_agg2[(size_t)NN * HD];
__device__ float g_sums[NG * HD];
__device__ float g_cnts[NG];

// ---------------------------------------------------------------------------
// Per-node precompute: v[n][o][d] = sum_i h[n][i] * W[d*256 + i*16 + o]
//                      bb[n][o]   = sum_i h[n][i] * b[i*16 + o]
//                      agg[n][o]  = bias[o] + sum_i h[n][i] * root[i*16 + o]
// 256 threads = 16 nodes/block, thread handles one (node, o).
// ---------------------------------------------------------------------------
template <bool RELU_IN>
__global__ void __launch_bounds__(256) prep_kernel(
    const float* __restrict__ h, const float* __restrict__ W,
    const float* __restrict__ b, const float* __restrict__ root,
    const float* __restrict__ bias,
    float* __restrict__ v, float* __restrict__ bb, float* __restrict__ agg)
{
    __shared__ float sW[ED * ND * HD];   // 8 KB
    __shared__ float sB[ND * HD];
    __shared__ float sR[ND * HD];
    __shared__ float sBias[HD];

    int tid = threadIdx.x;
    for (int i = tid; i < ED * ND * HD; i += 256) sW[i] = W[i];
    for (int i = tid; i < ND * HD; i += 256) { sB[i] = b[i]; sR[i] = root[i]; }
    if (tid < HD) sBias[tid] = bias[tid];
    __syncthreads();

    int node = blockIdx.x * 16 + (tid >> 4);
    if (node >= NN) return;
    int o = tid & 15;

    const float* hp = h + (size_t)node * 16;
    float hrow[16];
#pragma unroll
    for (int i = 0; i < 16; i++) {
        float t = __ldg(hp + i);
        hrow[i] = RELU_IN ? fmaxf(t, 0.f) : t;
    }

    float vr[8];
#pragma unroll
    for (int d = 0; d < 8; d++) vr[d] = 0.f;
    float bbv = 0.f;
    float rt = sBias[o];

#pragma unroll
    for (int i = 0; i < 16; i++) {
        float hv = hrow[i];
        int k = i * 16 + o;
#pragma unroll
        for (int d = 0; d < 8; d++)
            vr[d] = fmaf(hv, sW[d * 256 + k], vr[d]);
        bbv = fmaf(hv, sB[k], bbv);
        rt  = fmaf(hv, sR[k], rt);
    }

    float4* vp = reinterpret_cast<float4*>(v + ((size_t)node * 16 + o) * 8);
    vp[0] = make_float4(vr[0], vr[1], vr[2], vr[3]);
    vp[1] = make_float4(vr[4], vr[5], vr[6], vr[7]);
    bb[(size_t)node * 16 + o] = bbv;
    agg[(size_t)node * 16 + o] = rt;
}

// ---------------------------------------------------------------------------
// Edge kernel: 4 threads per edge; thread oq handles outputs [oq*4, oq*4+4).
//   msg[o] = bb[src][o] + sum_d ea[e][d] * v[src][o][d]
// scattered into agg[dst] with one red.global.add.v4.f32 per thread.
// ---------------------------------------------------------------------------
__global__ void __launch_bounds__(256) edge_kernel(
    const int* __restrict__ ei, const float* __restrict__ ea,
    const float* __restrict__ v, const float* __restrict__ bb,
    float* __restrict__ agg)
{
    int gid = blockIdx.x * blockDim.x + threadIdx.x;
    int e = gid >> 2;
    if (e >= EE) return;
    int oq = gid & 3;

    int src = __ldg(ei + e);
    int dst = __ldg(ei + EE + e);

    const float4* eap = reinterpret_cast<const float4*>(ea + (size_t)e * 8);
    float4 e0 = __ldg(eap);
    float4 e1 = __ldg(eap + 1);

    const float4* vp =
        reinterpret_cast<const float4*>(v + ((size_t)src * 16 + oq * 4) * 8);
    float4 bbv = __ldg(reinterpret_cast<const float4*>(bb + (size_t)src * 16 + oq * 4));
    float bbarr[4] = {bbv.x, bbv.y, bbv.z, bbv.w};

    float acc[4];
#pragma unroll
    for (int j = 0; j < 4; j++) {
        float4 a = __ldg(vp + j * 2);
        float4 c = __ldg(vp + j * 2 + 1);
        float s = bbarr[j];
        s = fmaf(e0.x, a.x, s); s = fmaf(e0.y, a.y, s);
        s = fmaf(e0.z, a.z, s); s = fmaf(e0.w, a.w, s);
        s = fmaf(e1.x, c.x, s); s = fmaf(e1.y, c.y, s);
        s = fmaf(e1.z, c.z, s); s = fmaf(e1.w, c.w, s);
        acc[j] = s;
    }

    float* ap = agg + (size_t)dst * 16 + oq * 4;
    asm volatile("red.global.add.v4.f32 [%0], {%1,%2,%3,%4};"
                 :: "l"(ap), "f"(acc[0]), "f"(acc[1]), "f"(acc[2]), "f"(acc[3])
                 : "memory");
}

// ---------------------------------------------------------------------------
// Pooling
// ---------------------------------------------------------------------------
__global__ void zero_pool_kernel()
{
    int t = blockIdx.x * blockDim.x + threadIdx.x;
    if (t < NG * HD) g_sums[t] = 0.f;
    if (t < NG) g_cnts[t] = 0.f;
}

__global__ void __launch_bounds__(256) pool_kernel(
    const float* __restrict__ agg, const int* __restrict__ batch)
{
    __shared__ float ssum[NG * HD];
    __shared__ float scnt[NG];
    int tid = threadIdx.x;
    for (int i = tid; i < NG * HD; i += blockDim.x) ssum[i] = 0.f;
    if (tid < NG) scnt[tid] = 0.f;
    __syncthreads();

    const int total = NN * HD;
    for (int idx = blockIdx.x * blockDim.x + tid; idx < total;
         idx += gridDim.x * blockDim.x) {
        int node = idx >> 4;
        int o = idx & 15;
        int g = __ldg(batch + node);
        float val = fmaxf(__ldg(agg + idx), 0.f);   // final ReLU fused here
        atomicAdd(&ssum[g * HD + o], val);
        if (o == 0) atomicAdd(&scnt[g], 1.f);
    }
    __syncthreads();
    for (int i = tid; i < NG * HD; i += blockDim.x)
        atomicAdd(&g_sums[i], ssum[i]);
    if (tid < NG) atomicAdd(&g_cnts[tid], scnt[tid]);
}

__global__ void final_kernel(float* __restrict__ out)
{
    int t = threadIdx.x;
    if (t < NG * HD) {
        float c = g_cnts[t >> 4];
        out[t] = g_sums[t] / fmaxf(c, 1.f);
    }
}

// ---------------------------------------------------------------------------
// Launch
// ---------------------------------------------------------------------------
extern "C" void kernel_launch(void* const* d_in, const int* in_sizes, int n_in,
                              void* d_out, int out_size)
{
    const float* x     = (const float*)d_in[0];
    const float* ea    = (const float*)d_in[1];
    const float* W1    = (const float*)d_in[2];
    const float* b1    = (const float*)d_in[3];
    const float* root1 = (const float*)d_in[4];
    const float* bias1 = (const float*)d_in[5];
    const float* W2    = (const float*)d_in[6];
    const float* b2    = (const float*)d_in[7];
    const float* root2 = (const float*)d_in[8];
    const float* bias2 = (const float*)d_in[9];
    const int*   ei    = (const int*)d_in[10];
    const int*   batch = (const int*)d_in[11];
    float* out = (float*)d_out;

    float *v, *bb, *agg1, *agg2;
    cudaGetSymbolAddress((void**)&v, g_v);
    cudaGetSymbolAddress((void**)&bb, g_bb);
    cudaGetSymbolAddress((void**)&agg1, g_agg1);
    cudaGetSymbolAddress((void**)&agg2, g_agg2);

    const int prep_grid = (NN + 15) / 16;
    const int edge_grid = (EE * 4 + 255) / 256;

    prep_kernel<false><<<prep_grid, 256>>>(x, W1, b1, root1, bias1, v, bb, agg1);
    edge_kernel<<<edge_grid, 256>>>(ei, ea, v, bb, agg1);
    prep_kernel<true><<<prep_grid, 256>>>(agg1, W2, b2, root2, bias2, v, bb, agg2);
    edge_kernel<<<edge_grid, 256>>>(ei, ea, v, bb, agg2);
    zero_pool_kernel<<<1, 512>>>();
    pool_kernel<<<296, 256>>>(agg2, batch);
    final_kernel<<<1, 512>>>(out);
}

// round 3
// speedup vs baseline: 1.5157x; 1.5157x over previous
#include <cuda_runtime.h>

#define NN 100000   // nodes
#define EE 500000   // edges
#define ND 16       // node_dim
#define ED 8        // edge_dim
#define HD 16       // hidden_dim
#define NG 32       // graphs

// Scratch (no allocation allowed -> __device__ globals)
__device__ __align__(128) float g_v[(size_t)NN * HD * ED];   // 51.2 MB: v[n][d][o]
__device__ __align__(128) float g_bb[(size_t)NN * HD];
__device__ __align__(128) float g_agg1[(size_t)NN * HD];
__device__ __align__(128) float g_agg2[(size_t)NN * HD];
__device__ float g_sums[NG * HD];
__device__ float g_cnts[NG];

// ---------------------------------------------------------------------------
// Per-node precompute:
//   v[n][d][o] = sum_i h[n][i] * W[d*256 + i*16 + o]
//   bb[n][o]   = sum_i h[n][i] * b[i*16 + o]
//   agg[n][o]  = bias[o] + sum_i h[n][i] * root[i*16 + o]
// 256 threads = 16 nodes/block, thread handles one (node, o).
// ---------------------------------------------------------------------------
template <bool RELU_IN, bool ZERO_POOL>
__global__ void __launch_bounds__(256) prep_kernel(
    const float* __restrict__ h, const float* __restrict__ W,
    const float* __restrict__ b, const float* __restrict__ root,
    const float* __restrict__ bias,
    float* __restrict__ v, float* __restrict__ bb, float* __restrict__ agg)
{
    __shared__ float sW[ED * ND * HD];   // 8 KB
    __shared__ float sB[ND * HD];
    __shared__ float sR[ND * HD];
    __shared__ float sBias[HD];

    int tid = threadIdx.x;
    if (ZERO_POOL && blockIdx.x == 0) {
        // NG*HD = 512 > blockDim -> must loop (round-2 bug was `if (tid < 512)`)
        for (int i = tid; i < NG * HD; i += 256) g_sums[i] = 0.f;
        if (tid < NG) g_cnts[tid] = 0.f;
    }
    for (int i = tid; i < ED * ND * HD; i += 256) sW[i] = W[i];
    for (int i = tid; i < ND * HD; i += 256) { sB[i] = b[i]; sR[i] = root[i]; }
    if (tid < HD) sBias[tid] = bias[tid];
    __syncthreads();

    int node = blockIdx.x * 16 + (tid >> 4);
    if (node >= NN) return;
    int o = tid & 15;

    const float* hp = h + (size_t)node * 16;
    float hrow[16];
#pragma unroll
    for (int i = 0; i < 16; i++) {
        float t = __ldg(hp + i);
        hrow[i] = RELU_IN ? fmaxf(t, 0.f) : t;
    }

    float vr[8];
#pragma unroll
    for (int d = 0; d < 8; d++) vr[d] = 0.f;
    float bbv = 0.f;
    float rt = sBias[o];

#pragma unroll
    for (int i = 0; i < 16; i++) {
        float hv = hrow[i];
        int k = i * 16 + o;
#pragma unroll
        for (int d = 0; d < 8; d++)
            vr[d] = fmaf(hv, sW[d * 256 + k], vr[d]);
        bbv = fmaf(hv, sB[k], bbv);
        rt  = fmaf(hv, sR[k], rt);
    }

    // d-major layout: float index node*128 + d*16 + o (coalesced per (node,d))
    float* vb = v + (size_t)node * 128 + o;
#pragma unroll
    for (int d = 0; d < 8; d++)
        vb[d * 16] = vr[d];
    bb[(size_t)node * 16 + o] = bbv;
    agg[(size_t)node * 16 + o] = rt;
}

// ---------------------------------------------------------------------------
// Edge kernel: 8 lanes per edge. Lane r reads float4 at byte offset
// l*128 + r*16 of v[src] for lines l=0..3 -> each LDG covers full 128B lines.
//   lane r holds d = 2l + (r>>2), o-quad q = r&3.
//   partial[q] = sum over its 4 d's of ea[d]*v[d][q*4..q*4+4)
//   full = partial + shfl_xor(partial, 4); lanes r<4 add bb and scatter.
// ---------------------------------------------------------------------------
__global__ void __launch_bounds__(256) edge_kernel(
    const int* __restrict__ ei, const float* __restrict__ ea,
    const float* __restrict__ v, const float* __restrict__ bb,
    float* __restrict__ agg)
{
    int gid = blockIdx.x * 256 + threadIdx.x;
    int e = gid >> 3;
    if (e >= EE) return;
    int r = gid & 7;
    int hlf = r >> 2;     // 0: even d, 1: odd d
    int q = r & 3;        // output quad

    int src = __ldg(ei + e);
    int dst = __ldg(ei + EE + e);

    const float4* eap = reinterpret_cast<const float4*>(ea + (size_t)e * 8);
    float4 ea0 = __ldg(eap);
    float4 ea1 = __ldg(eap + 1);
    // coefficients for this lane's d = {hlf, hlf+2, hlf+4, hlf+6}
    float c0 = hlf ? ea0.y : ea0.x;
    float c1 = hlf ? ea0.w : ea0.z;
    float c2 = hlf ? ea1.y : ea1.x;
    float c3 = hlf ? ea1.w : ea1.z;

    const float4* vp = reinterpret_cast<const float4*>(v + (size_t)src * 128) + r;
    float4 v0 = __ldg(vp);        // line 0: d = hlf
    float4 v1 = __ldg(vp + 8);    // line 1: d = 2 + hlf
    float4 v2 = __ldg(vp + 16);   // line 2: d = 4 + hlf
    float4 v3 = __ldg(vp + 24);   // line 3: d = 6 + hlf

    float ax = fmaf(c0, v0.x, fmaf(c1, v1.x, fmaf(c2, v2.x, c3 * v3.x)));
    float ay = fmaf(c0, v0.y, fmaf(c1, v1.y, fmaf(c2, v2.y, c3 * v3.y)));
    float az = fmaf(c0, v0.z, fmaf(c1, v1.z, fmaf(c2, v2.z, c3 * v3.z)));
    float aw = fmaf(c0, v0.w, fmaf(c1, v1.w, fmaf(c2, v2.w, c3 * v3.w)));

    ax += __shfl_xor_sync(0xffffffffu, ax, 4);
    ay += __shfl_xor_sync(0xffffffffu, ay, 4);
    az += __shfl_xor_sync(0xffffffffu, az, 4);
    aw += __shfl_xor_sync(0xffffffffu, aw, 4);

    if (hlf == 0) {
        float4 bbq = __ldg(reinterpret_cast<const float4*>(bb + (size_t)src * 16) + q);
        ax += bbq.x; ay += bbq.y; az += bbq.z; aw += bbq.w;
        float* ap = agg + (size_t)dst * 16 + q * 4;
        asm volatile("red.global.add.v4.f32 [%0], {%1,%2,%3,%4};"
                     :: "l"(ap), "f"(ax), "f"(ay), "f"(az), "f"(aw)
                     : "memory");
    }
}

// ---------------------------------------------------------------------------
// Pooling: batch is sorted, so register-accumulate runs and flush on
// graph-id change. Warp = 2 half-warps, each half handles 32 contiguous
// nodes; lane's o = lane&15. Final ReLU fused here.
// ---------------------------------------------------------------------------
#define POOL_NODES_PER_HALF 32
__global__ void __launch_bounds__(256) pool_kernel(
    const float* __restrict__ agg, const int* __restrict__ batch)
{
    int gwarp = (blockIdx.x * 256 + threadIdx.x) >> 5;
    int lane = threadIdx.x & 31;
    int o = lane & 15;
    int sub = lane >> 4;
    int base = (gwarp * 2 + sub) * POOL_NODES_PER_HALF;

    float rsum = 0.f, rcnt = 0.f;
    int curg = -1;
#pragma unroll 4
    for (int k = 0; k < POOL_NODES_PER_HALF; k++) {
        int node = base + k;
        if (node >= NN) break;
        int g = __ldg(batch + node);
        if (g != curg) {
            if (curg >= 0) {
                atomicAdd(&g_sums[curg * HD + o], rsum);
                if (o == 0) atomicAdd(&g_cnts[curg], rcnt);
            }
            curg = g; rsum = 0.f; rcnt = 0.f;
        }
        rsum += fmaxf(__ldg(agg + (size_t)node * 16 + o), 0.f);
        rcnt += 1.f;
    }
    if (curg >= 0) {
        atomicAdd(&g_sums[curg * HD + o], rsum);
        if (o == 0) atomicAdd(&g_cnts[curg], rcnt);
    }
}

__global__ void final_kernel(float* __restrict__ out)
{
    int t = threadIdx.x;
    if (t < NG * HD) {
        float c = g_cnts[t >> 4];
        out[t] = g_sums[t] / fmaxf(c, 1.f);
    }
}

// ---------------------------------------------------------------------------
// Launch
// ---------------------------------------------------------------------------
extern "C" void kernel_launch(void* const* d_in, const int* in_sizes, int n_in,
                              void* d_out, int out_size)
{
    const float* x     = (const float*)d_in[0];
    const float* ea    = (const float*)d_in[1];
    const float* W1    = (const float*)d_in[2];
    const float* b1    = (const float*)d_in[3];
    const float* root1 = (const float*)d_in[4];
    const float* bias1 = (const float*)d_in[5];
    const float* W2    = (const float*)d_in[6];
    const float* b2    = (const float*)d_in[7];
    const float* root2 = (const float*)d_in[8];
    const float* bias2 = (const float*)d_in[9];
    const int*   ei    = (const int*)d_in[10];
    const int*   batch = (const int*)d_in[11];
    float* out = (float*)d_out;

    float *v, *bb, *agg1, *agg2;
    cudaGetSymbolAddress((void**)&v, g_v);
    cudaGetSymbolAddress((void**)&bb, g_bb);
    cudaGetSymbolAddress((void**)&agg1, g_agg1);
    cudaGetSymbolAddress((void**)&agg2, g_agg2);

    const int prep_grid = (NN + 15) / 16;
    const int edge_grid = (EE * 8 + 255) / 256;
    const int pool_halves = (NN + POOL_NODES_PER_HALF - 1) / POOL_NODES_PER_HALF;
    const int pool_grid = (pool_halves / 2 + 7) / 8 + 1;

    prep_kernel<false, true><<<prep_grid, 256>>>(x, W1, b1, root1, bias1, v, bb, agg1);
    edge_kernel<<<edge_grid, 256>>>(ei, ea, v, bb, agg1);
    prep_kernel<true, false><<<prep_grid, 256>>>(agg1, W2, b2, root2, bias2, v, bb, agg2);
    edge_kernel<<<edge_grid, 256>>>(ei, ea, v, bb, agg2);
    pool_kernel<<<pool_grid, 256>>>(agg2, batch);
    final_kernel<<<1, 512>>>(out);
}

// round 4
// speedup vs baseline: 1.8901x; 1.2470x over previous
#include <cuda_runtime.h>

#define NN 100000   // nodes
#define EE 500000   // edges
#define ND 16       // node_dim
#define ED 8        // edge_dim
#define HD 16       // hidden_dim
#define NG 32       // graphs

// Scratch (no allocation allowed -> __device__ globals)
__device__ __align__(128) float g_v[(size_t)NN * HD * ED];   // 51.2 MB: v[n][d][o]
__device__ __align__(128) float g_bb[(size_t)NN * HD];
__device__ __align__(128) float g_agg1[(size_t)NN * HD];
__device__ __align__(128) float g_agg2[(size_t)NN * HD];
__device__ float g_sums[NG * HD];
__device__ float g_cnts[NG];

// ---------------------------------------------------------------------------
// Prep v2: 64 nodes/block, thread (o = tid&15, ng = tid>>4) computes 4 nodes.
//   v[n][d][o] = sum_i h[n][i] * W[d*256 + i*16 + o]   (d-major layout)
//   bb[n][o]   = sum_i h[n][i] * b[i*16 + o]
//   agg[n][o]  = bias[o] + sum_i h[n][i] * root[i*16 + o]
// v written via smem exchange -> coalesced STG.128.
// ---------------------------------------------------------------------------
template <bool RELU_IN, bool ZERO_POOL>
__global__ void __launch_bounds__(256) prep_kernel(
    const float* __restrict__ h, const float* __restrict__ W,
    const float* __restrict__ b, const float* __restrict__ root,
    const float* __restrict__ bias,
    float* __restrict__ v, float* __restrict__ bb, float* __restrict__ agg)
{
    __shared__ float sW[ED * ND * HD];   // 8 KB
    __shared__ float sB[ND * HD];
    __shared__ float sR[ND * HD];
    __shared__ float sBias[HD];
    __shared__ float sH[64 * 16];        // 4 KB staged h tile
    __shared__ float sV[64 * 128];       // 32 KB exchange

    int tid = threadIdx.x;
    if (ZERO_POOL && blockIdx.x == 0) {
        for (int i = tid; i < NG * HD; i += 256) g_sums[i] = 0.f;
        if (tid < NG) g_cnts[tid] = 0.f;
    }
    for (int i = tid; i < ED * ND * HD; i += 256) sW[i] = W[i];
    for (int i = tid; i < ND * HD; i += 256) { sB[i] = b[i]; sR[i] = root[i]; }
    if (tid < HD) sBias[tid] = bias[tid];

    int nodeBase = blockIdx.x * 64;
    // stage h tile: 64 nodes x 16 floats = 256 float4
    {
        int node = nodeBase + (tid >> 2);
        int quad = tid & 3;
        float4 hv = make_float4(0.f, 0.f, 0.f, 0.f);
        if (node < NN)
            hv = __ldg(reinterpret_cast<const float4*>(h + (size_t)node * 16) + quad);
        if (RELU_IN) {
            hv.x = fmaxf(hv.x, 0.f); hv.y = fmaxf(hv.y, 0.f);
            hv.z = fmaxf(hv.z, 0.f); hv.w = fmaxf(hv.w, 0.f);
        }
        reinterpret_cast<float4*>(sH)[tid] = hv;
    }
    __syncthreads();

    int o = tid & 15;
    int ng = tid >> 4;   // 0..15, owns nodes nodeBase + ng*4 .. +3

    float vr[4][8];
    float bbv[4];
    float rt[4];
#pragma unroll
    for (int j = 0; j < 4; j++) {
        bbv[j] = 0.f; rt[j] = sBias[o];
#pragma unroll
        for (int d = 0; d < 8; d++) vr[j][d] = 0.f;
    }

#pragma unroll
    for (int i = 0; i < 16; i++) {
        int k = i * 16 + o;
        float w[8];
#pragma unroll
        for (int d = 0; d < 8; d++) w[d] = sW[d * 256 + k];
        float bw = sB[k];
        float rw = sR[k];
#pragma unroll
        for (int j = 0; j < 4; j++) {
            float hv = sH[(ng * 4 + j) * 16 + i];
#pragma unroll
            for (int d = 0; d < 8; d++)
                vr[j][d] = fmaf(hv, w[d], vr[j][d]);
            bbv[j] = fmaf(hv, bw, bbv[j]);
            rt[j]  = fmaf(hv, rw, rt[j]);
        }
    }

    // exchange: sV[local_node][d][o]
#pragma unroll
    for (int j = 0; j < 4; j++)
#pragma unroll
        for (int d = 0; d < 8; d++)
            sV[(ng * 4 + j) * 128 + d * 16 + o] = vr[j][d];

    // direct stores for bb/agg (small arrays)
#pragma unroll
    for (int j = 0; j < 4; j++) {
        int node = nodeBase + ng * 4 + j;
        if (node < NN) {
            bb[(size_t)node * 16 + o] = bbv[j];
            agg[(size_t)node * 16 + o] = rt[j];
        }
    }
    __syncthreads();

    // coalesced v store: 64 nodes * 32 float4 = 2048 float4
    int nvalid4 = (NN - nodeBase < 64 ? NN - nodeBase : 64) * 32;
    float4* vout = reinterpret_cast<float4*>(v + (size_t)nodeBase * 128);
    const float4* sv4 = reinterpret_cast<const float4*>(sV);
#pragma unroll
    for (int k = 0; k < 8; k++) {
        int idx = k * 256 + tid;
        if (idx < nvalid4) vout[idx] = sv4[idx];
    }
}

// ---------------------------------------------------------------------------
// Edge kernel: 8 lanes per edge, 2 edges per thread (MLP doubling).
// Lane r reads float4 at byte offset l*128 + r*16 of v[src] (full 128B lines).
//   lane r holds d = 2l + (r>>2), o-quad q = r&3.
//   full = partial + shfl_xor(partial, 4); lanes r<4 add bb and scatter.
// ---------------------------------------------------------------------------
__global__ void __launch_bounds__(256) edge_kernel(
    const int* __restrict__ ei, const float* __restrict__ ea,
    const float* __restrict__ v, const float* __restrict__ bb,
    float* __restrict__ agg)
{
    const int HALF = EE / 2;
    int gid = blockIdx.x * 256 + threadIdx.x;
    int p = gid >> 3;
    if (p >= HALF) return;
    int r = gid & 7;
    int hlf = r >> 2;
    int q = r & 3;

    int e0 = p;
    int e1 = p + HALF;

    int src0 = __ldg(ei + e0);
    int dst0 = __ldg(ei + EE + e0);
    int src1 = __ldg(ei + e1);
    int dst1 = __ldg(ei + EE + e1);

    const float4* ep0 = reinterpret_cast<const float4*>(ea + (size_t)e0 * 8);
    const float4* ep1 = reinterpret_cast<const float4*>(ea + (size_t)e1 * 8);
    float4 a00 = __ldg(ep0), a01 = __ldg(ep0 + 1);
    float4 a10 = __ldg(ep1), a11 = __ldg(ep1 + 1);

    const float4* vp0 = reinterpret_cast<const float4*>(v + (size_t)src0 * 128) + r;
    const float4* vp1 = reinterpret_cast<const float4*>(v + (size_t)src1 * 128) + r;
    float4 v00 = __ldg(vp0),      v01 = __ldg(vp0 + 8),
           v02 = __ldg(vp0 + 16), v03 = __ldg(vp0 + 24);
    float4 v10 = __ldg(vp1),      v11 = __ldg(vp1 + 8),
           v12 = __ldg(vp1 + 16), v13 = __ldg(vp1 + 24);

    // edge 0 coefficients for this lane's d = {hlf, 2+hlf, 4+hlf, 6+hlf}
    float c0 = hlf ? a00.y : a00.x, c1 = hlf ? a00.w : a00.z;
    float c2 = hlf ? a01.y : a01.x, c3 = hlf ? a01.w : a01.z;
    float d0 = hlf ? a10.y : a10.x, d1 = hlf ? a10.w : a10.z;
    float d2 = hlf ? a11.y : a11.x, d3 = hlf ? a11.w : a11.z;

    float x0 = fmaf(c0, v00.x, fmaf(c1, v01.x, fmaf(c2, v02.x, c3 * v03.x)));
    float y0 = fmaf(c0, v00.y, fmaf(c1, v01.y, fmaf(c2, v02.y, c3 * v03.y)));
    float z0 = fmaf(c0, v00.z, fmaf(c1, v01.z, fmaf(c2, v02.z, c3 * v03.z)));
    float w0 = fmaf(c0, v00.w, fmaf(c1, v01.w, fmaf(c2, v02.w, c3 * v03.w)));

    float x1 = fmaf(d0, v10.x, fmaf(d1, v11.x, fmaf(d2, v12.x, d3 * v13.x)));
    float y1 = fmaf(d0, v10.y, fmaf(d1, v11.y, fmaf(d2, v12.y, d3 * v13.y)));
    float z1 = fmaf(d0, v10.z, fmaf(d1, v11.z, fmaf(d2, v12.z, d3 * v13.z)));
    float w1 = fmaf(d0, v10.w, fmaf(d1, v11.w, fmaf(d2, v12.w, d3 * v13.w)));

    x0 += __shfl_xor_sync(0xffffffffu, x0, 4);
    y0 += __shfl_xor_sync(0xffffffffu, y0, 4);
    z0 += __shfl_xor_sync(0xffffffffu, z0, 4);
    w0 += __shfl_xor_sync(0xffffffffu, w0, 4);
    x1 += __shfl_xor_sync(0xffffffffu, x1, 4);
    y1 += __shfl_xor_sync(0xffffffffu, y1, 4);
    z1 += __shfl_xor_sync(0xffffffffu, z1, 4);
    w1 += __shfl_xor_sync(0xffffffffu, w1, 4);

    if (hlf == 0) {
        float4 b0 = __ldg(reinterpret_cast<const float4*>(bb + (size_t)src0 * 16) + q);
        float4 b1 = __ldg(reinterpret_cast<const float4*>(bb + (size_t)src1 * 16) + q);
        x0 += b0.x; y0 += b0.y; z0 += b0.z; w0 += b0.w;
        x1 += b1.x; y1 += b1.y; z1 += b1.z; w1 += b1.w;
        float* ap0 = agg + (size_t)dst0 * 16 + q * 4;
        float* ap1 = agg + (size_t)dst1 * 16 + q * 4;
        asm volatile("red.global.add.v4.f32 [%0], {%1,%2,%3,%4};"
                     :: "l"(ap0), "f"(x0), "f"(y0), "f"(z0), "f"(w0) : "memory");
        asm volatile("red.global.add.v4.f32 [%0], {%1,%2,%3,%4};"
                     :: "l"(ap1), "f"(x1), "f"(y1), "f"(z1), "f"(w1) : "memory");
    }
}

// ---------------------------------------------------------------------------
// Pooling: batch sorted -> register-accumulate runs, flush on change.
// ---------------------------------------------------------------------------
#define POOL_NODES_PER_HALF 32
__global__ void __launch_bounds__(256) pool_kernel(
    const float* __restrict__ agg, const int* __restrict__ batch)
{
    int gwarp = (blockIdx.x * 256 + threadIdx.x) >> 5;
    int lane = threadIdx.x & 31;
    int o = lane & 15;
    int sub = lane >> 4;
    int base = (gwarp * 2 + sub) * POOL_NODES_PER_HALF;

    float rsum = 0.f, rcnt = 0.f;
    int curg = -1;
#pragma unroll 4
    for (int k = 0; k < POOL_NODES_PER_HALF; k++) {
        int node = base + k;
        if (node >= NN) break;
        int g = __ldg(batch + node);
        if (g != curg) {
            if (curg >= 0) {
                atomicAdd(&g_sums[curg * HD + o], rsum);
                if (o == 0) atomicAdd(&g_cnts[curg], rcnt);
            }
            curg = g; rsum = 0.f; rcnt = 0.f;
        }
        rsum += fmaxf(__ldg(agg + (size_t)node * 16 + o), 0.f);
        rcnt += 1.f;
    }
    if (curg >= 0) {
        atomicAdd(&g_sums[curg * HD + o], rsum);
        if (o == 0) atomicAdd(&g_cnts[curg], rcnt);
    }
}

__global__ void final_kernel(float* __restrict__ out)
{
    int t = threadIdx.x;
    if (t < NG * HD) {
        float c = g_cnts[t >> 4];
        out[t] = g_sums[t] / fmaxf(c, 1.f);
    }
}

// ---------------------------------------------------------------------------
// Launch
// ---------------------------------------------------------------------------
extern "C" void kernel_launch(void* const* d_in, const int* in_sizes, int n_in,
                              void* d_out, int out_size)
{
    const float* x     = (const float*)d_in[0];
    const float* ea    = (const float*)d_in[1];
    const float* W1    = (const float*)d_in[2];
    const float* b1    = (const float*)d_in[3];
    const float* root1 = (const float*)d_in[4];
    const float* bias1 = (const float*)d_in[5];
    const float* W2    = (const float*)d_in[6];
    const float* b2    = (const float*)d_in[7];
    const float* root2 = (const float*)d_in[8];
    const float* bias2 = (const float*)d_in[9];
    const int*   ei    = (const int*)d_in[10];
    const int*   batch = (const int*)d_in[11];
    float* out = (float*)d_out;

    float *v, *bb, *agg1, *agg2;
    cudaGetSymbolAddress((void**)&v, g_v);
    cudaGetSymbolAddress((void**)&bb, g_bb);
    cudaGetSymbolAddress((void**)&agg1, g_agg1);
    cudaGetSymbolAddress((void**)&agg2, g_agg2);

    const int prep_grid = (NN + 63) / 64;
    const int edge_grid = ((EE / 2) * 8 + 255) / 256;
    const int pool_halves = (NN + POOL_NODES_PER_HALF - 1) / POOL_NODES_PER_HALF;
    const int pool_grid = (pool_halves / 2 + 7) / 8 + 1;

    prep_kernel<false, true><<<prep_grid, 256>>>(x, W1, b1, root1, bias1, v, bb, agg1);
    edge_kernel<<<edge_grid, 256>>>(ei, ea, v, bb, agg1);
    prep_kernel<true, false><<<prep_grid, 256>>>(agg1, W2, b2, root2, bias2, v, bb, agg2);
    edge_kernel<<<edge_grid, 256>>>(ei, ea, v, bb, agg2);
    pool_kernel<<<pool_grid, 256>>>(agg2, batch);
    final_kernel<<<1, 512>>>(out);
}

// round 5
// speedup vs baseline: 2.0440x; 1.0815x over previous
#include <cuda_runtime.h>

#define NN 100000   // nodes
#define EE 500000   // edges
#define ND 16       // node_dim
#define ED 8        // edge_dim
#define HD 16       // hidden_dim
#define NG 32       // graphs

// Scratch (no allocation allowed -> __device__ globals)
__device__ __align__(128) float g_v[(size_t)NN * HD * ED];   // 51.2 MB: v[n][d][o]
__device__ __align__(128) float g_bb[(size_t)NN * HD];
__device__ __align__(128) float g_agg1[(size_t)NN * HD];
__device__ __align__(128) float g_agg2[(size_t)NN * HD];
__device__ float g_sums[NG * HD];
__device__ float g_cnts[NG];

// ---------------------------------------------------------------------------
// Prep v3: 32 nodes/block, 256 threads. Thread (ng=tid>>5, d=(tid>>2)&7,
// q=tid&3) computes v[n][d][q*4..q*4+3] as a float4 for 4 nodes
// (n = base + ng*4 + j), storing with fully-coalesced STG.128 (no exchange).
// Threads d<4 also compute agg[n][o2], threads d>=4 compute bb[n][o2],
// o2 = (d&3)*4 + q (bijective over 0..15 per half).
//   v[n][d][o] = sum_i h[n][i] * W[d*256 + i*16 + o]
//   bb[n][o]   = sum_i h[n][i] * b[i*16 + o]
//   agg[n][o]  = bias[o] + sum_i h[n][i] * root[i*16 + o]
// ---------------------------------------------------------------------------
template <bool RELU_IN, bool ZERO_POOL>
__global__ void __launch_bounds__(256) prep_kernel(
    const float* __restrict__ h, const float* __restrict__ W,
    const float* __restrict__ b, const float* __restrict__ root,
    const float* __restrict__ bias,
    float* __restrict__ v, float* __restrict__ bb, float* __restrict__ agg)
{
    __shared__ float4 sW4[ED * ND * HD / 4];   // 512 float4 = 8 KB
    __shared__ float sR[ND * HD];
    __shared__ float sB[ND * HD];
    __shared__ float sBias[HD];
    __shared__ float sH[32 * 16];              // 2 KB staged h tile

    int tid = threadIdx.x;
    if (ZERO_POOL && blockIdx.x == 0) {
        for (int i = tid; i < NG * HD; i += 256) g_sums[i] = 0.f;
        if (tid < NG) g_cnts[tid] = 0.f;
    }
    for (int i = tid; i < 512; i += 256)
        sW4[i] = __ldg(reinterpret_cast<const float4*>(W) + i);
    for (int i = tid; i < 256; i += 256) { sR[i] = root[i]; sB[i] = b[i]; }
    if (tid < HD) sBias[tid] = bias[tid];

    int nodeBase = blockIdx.x * 32;
    if (tid < 128) {
        int node = nodeBase + (tid >> 2);
        float4 hv = make_float4(0.f, 0.f, 0.f, 0.f);
        if (node < NN)
            hv = __ldg(reinterpret_cast<const float4*>(h) + (size_t)node * 4 + (tid & 3));
        if (RELU_IN) {
            hv.x = fmaxf(hv.x, 0.f); hv.y = fmaxf(hv.y, 0.f);
            hv.z = fmaxf(hv.z, 0.f); hv.w = fmaxf(hv.w, 0.f);
        }
        reinterpret_cast<float4*>(sH)[tid] = hv;
    }
    __syncthreads();

    int ng = tid >> 5;        // 0..7 (one warp = one node group)
    int d  = (tid >> 2) & 7;
    int q  = tid & 3;
    bool isAgg = d < 4;
    int o2 = (d & 3) * 4 + q;

    float4 acc[4];
    float sacc[4];
#pragma unroll
    for (int j = 0; j < 4; j++) {
        acc[j] = make_float4(0.f, 0.f, 0.f, 0.f);
        sacc[j] = isAgg ? sBias[o2] : 0.f;
    }

#pragma unroll
    for (int i = 0; i < 16; i++) {
        float4 wv = sW4[d * 64 + i * 4 + q];
        float rb = isAgg ? sR[i * 16 + o2] : sB[i * 16 + o2];
#pragma unroll
        for (int j = 0; j < 4; j++) {
            float hv = sH[(ng * 4 + j) * 16 + i];   // warp-broadcast
            acc[j].x = fmaf(hv, wv.x, acc[j].x);
            acc[j].y = fmaf(hv, wv.y, acc[j].y);
            acc[j].z = fmaf(hv, wv.z, acc[j].z);
            acc[j].w = fmaf(hv, wv.w, acc[j].w);
            sacc[j] = fmaf(hv, rb, sacc[j]);
        }
    }

    float4* vout = reinterpret_cast<float4*>(v) + (size_t)nodeBase * 32;
#pragma unroll
    for (int j = 0; j < 4; j++) {
        int nl = ng * 4 + j;
        int node = nodeBase + nl;
        if (node < NN) {
            vout[nl * 32 + d * 4 + q] = acc[j];          // 512B/node coalesced
            if (isAgg) agg[(size_t)node * 16 + o2] = sacc[j];
            else       bb[(size_t)node * 16 + o2] = sacc[j];
        }
    }
}

// ---------------------------------------------------------------------------
// Edge kernel v3: 8 lanes per edge, NO shfl. Lane r reads float4 at byte
// offset l*128 + r*16 of v[src] (full 128B lines). Lane r holds
// d = 2l + (r>>2), o-quad q = r&3. Each lane fires its partial directly as
// red.global.add.v4 (atomic add is associative); hlf==0 lanes fold in bb.
// ---------------------------------------------------------------------------
__global__ void __launch_bounds__(256) edge_kernel(
    const int* __restrict__ ei, const float* __restrict__ ea,
    const float* __restrict__ v, const float* __restrict__ bb,
    float* __restrict__ agg)
{
    int gid = blockIdx.x * 256 + threadIdx.x;
    int e = gid >> 3;
    if (e >= EE) return;
    int r = gid & 7;
    int hlf = r >> 2;     // 0: even d, 1: odd d
    int q = r & 3;        // output quad

    int src = __ldg(ei + e);
    int dst = __ldg(ei + EE + e);

    const float4* eap = reinterpret_cast<const float4*>(ea + (size_t)e * 8);
    float4 ea0 = __ldg(eap);
    float4 ea1 = __ldg(eap + 1);
    float c0 = hlf ? ea0.y : ea0.x;
    float c1 = hlf ? ea0.w : ea0.z;
    float c2 = hlf ? ea1.y : ea1.x;
    float c3 = hlf ? ea1.w : ea1.z;

    const float4* vp = reinterpret_cast<const float4*>(v + (size_t)src * 128) + r;
    float4 v0 = __ldg(vp);        // d = hlf
    float4 v1 = __ldg(vp + 8);    // d = 2 + hlf
    float4 v2 = __ldg(vp + 16);   // d = 4 + hlf
    float4 v3 = __ldg(vp + 24);   // d = 6 + hlf

    float ax = fmaf(c0, v0.x, fmaf(c1, v1.x, fmaf(c2, v2.x, c3 * v3.x)));
    float ay = fmaf(c0, v0.y, fmaf(c1, v1.y, fmaf(c2, v2.y, c3 * v3.y)));
    float az = fmaf(c0, v0.z, fmaf(c1, v1.z, fmaf(c2, v2.z, c3 * v3.z)));
    float aw = fmaf(c0, v0.w, fmaf(c1, v1.w, fmaf(c2, v2.w, c3 * v3.w)));

    if (hlf == 0) {
        float4 bbq = __ldg(reinterpret_cast<const float4*>(bb + (size_t)src * 16) + q);
        ax += bbq.x; ay += bbq.y; az += bbq.z; aw += bbq.w;
    }

    float* ap = agg + (size_t)dst * 16 + q * 4;
    asm volatile("red.global.add.v4.f32 [%0], {%1,%2,%3,%4};"
                 :: "l"(ap), "f"(ax), "f"(ay), "f"(az), "f"(aw)
                 : "memory");
}

// ---------------------------------------------------------------------------
// Pooling: batch sorted -> register-accumulate runs, flush on change.
// ---------------------------------------------------------------------------
#define POOL_NODES_PER_HALF 32
__global__ void __launch_bounds__(256) pool_kernel(
    const float* __restrict__ agg, const int* __restrict__ batch)
{
    int gwarp = (blockIdx.x * 256 + threadIdx.x) >> 5;
    int lane = threadIdx.x & 31;
    int o = lane & 15;
    int sub = lane >> 4;
    int base = (gwarp * 2 + sub) * POOL_NODES_PER_HALF;

    float rsum = 0.f, rcnt = 0.f;
    int curg = -1;
#pragma unroll 4
    for (int k = 0; k < POOL_NODES_PER_HALF; k++) {
        int node = base + k;
        if (node >= NN) break;
        int g = __ldg(batch + node);
        if (g != curg) {
            if (curg >= 0) {
                atomicAdd(&g_sums[curg * HD + o], rsum);
                if (o == 0) atomicAdd(&g_cnts[curg], rcnt);
            }
            curg = g; rsum = 0.f; rcnt = 0.f;
        }
        rsum += fmaxf(__ldg(agg + (size_t)node * 16 + o), 0.f);
        rcnt += 1.f;
    }
    if (curg >= 0) {
        atomicAdd(&g_sums[curg * HD + o], rsum);
        if (o == 0) atomicAdd(&g_cnts[curg], rcnt);
    }
}

__global__ void final_kernel(float* __restrict__ out)
{
    int t = threadIdx.x;
    if (t < NG * HD) {
        float c = g_cnts[t >> 4];
        out[t] = g_sums[t] / fmaxf(c, 1.f);
    }
}

// ---------------------------------------------------------------------------
// Launch
// ---------------------------------------------------------------------------
extern "C" void kernel_launch(void* const* d_in, const int* in_sizes, int n_in,
                              void* d_out, int out_size)
{
    const float* x     = (const float*)d_in[0];
    const float* ea    = (const float*)d_in[1];
    const float* W1    = (const float*)d_in[2];
    const float* b1    = (const float*)d_in[3];
    const float* root1 = (const float*)d_in[4];
    const float* bias1 = (const float*)d_in[5];
    const float* W2    = (const float*)d_in[6];
    const float* b2    = (const float*)d_in[7];
    const float* root2 = (const float*)d_in[8];
    const float* bias2 = (const float*)d_in[9];
    const int*   ei    = (const int*)d_in[10];
    const int*   batch = (const int*)d_in[11];
    float* out = (float*)d_out;

    float *v, *bb, *agg1, *agg2;
    cudaGetSymbolAddress((void**)&v, g_v);
    cudaGetSymbolAddress((void**)&bb, g_bb);
    cudaGetSymbolAddress((void**)&agg1, g_agg1);
    cudaGetSymbolAddress((void**)&agg2, g_agg2);

    const int prep_grid = (NN + 31) / 32;
    const int edge_grid = (EE * 8 + 255) / 256;
    const int pool_halves = (NN + POOL_NODES_PER_HALF - 1) / POOL_NODES_PER_HALF;
    const int pool_grid = (pool_halves / 2 + 7) / 8 + 1;

    prep_kernel<false, true><<<prep_grid, 256>>>(x, W1, b1, root1, bias1, v, bb, agg1);
    edge_kernel<<<edge_grid, 256>>>(ei, ea, v, bb, agg1);
    prep_kernel<true, false><<<prep_grid, 256>>>(agg1, W2, b2, root2, bias2, v, bb, agg2);
    edge_kernel<<<edge_grid, 256>>>(ei, ea, v, bb, agg2);
    pool_kernel<<<pool_grid, 256>>>(agg2, batch);
    final_kernel<<<1, 512>>>(out);
}